// round 2
// baseline (speedup 1.0000x reference)
#include <cuda_runtime.h>

// Scratch (no allocation allowed): per-node gate values, N = 100000 <= 131072.
#define MAX_NODES (1 << 17)
__device__ float g_gate[MAX_NODES];
__device__ int   g_is64;   // 1 if edge_index is int64, 0 if int32

// ---------------------------------------------------------------------------
// Kernel 0: detect index width. If int64, high 32 bits of every entry are 0
// (node ids < 2^31). If int32, odd int32 positions are random node ids, so
// "all of the first 2048 odd words are zero" has probability ~0.
// ---------------------------------------------------------------------------
__global__ void detect_kernel(const int* __restrict__ ei32, int total_words) {
    __shared__ int nz;
    if (threadIdx.x == 0) nz = 0;
    __syncthreads();
    int limit = 2048;
    if (limit * 2 > total_words) limit = total_words / 2;
    int c = 0;
    for (int i = threadIdx.x; i < limit; i += blockDim.x)
        if (ei32[2 * i + 1] != 0) c = 1;
    if (c) atomicOr(&nz, 1);
    __syncthreads();
    if (threadIdx.x == 0) g_is64 = (nz == 0) ? 1 : 0;
}

// ---------------------------------------------------------------------------
// Kernel 1: gate[n] = sigmoid(dot(x[n,:], p) + b). Warp-per-row GEMV,
// p staged in shared, x read once coalesced via float4 -> HBM-bound.
// ---------------------------------------------------------------------------
__global__ void gate_kernel(const float* __restrict__ x,
                            const float* __restrict__ p,
                            const float* __restrict__ bptr,
                            int N, int D) {
    __shared__ float p_sh[1024];
    int tid = threadIdx.x;
    for (int i = tid; i < D; i += blockDim.x) p_sh[i] = p[i];
    __syncthreads();

    int warp = tid >> 5;
    int lane = tid & 31;
    int row  = blockIdx.x * (blockDim.x >> 5) + warp;
    if (row >= N) return;

    const float4* xr = reinterpret_cast<const float4*>(x + (long long)row * D);
    float sum = 0.0f;
    int nvec = D >> 2;
    for (int i = lane; i < nvec; i += 32) {
        float4 xv = xr[i];
        float4 pv = reinterpret_cast<const float4*>(p_sh)[i];
        sum = fmaf(xv.x, pv.x, sum);
        sum = fmaf(xv.y, pv.y, sum);
        sum = fmaf(xv.z, pv.z, sum);
        sum = fmaf(xv.w, pv.w, sum);
    }
    #pragma unroll
    for (int o = 16; o > 0; o >>= 1)
        sum += __shfl_down_sync(0xffffffffu, sum, o);

    if (lane == 0) {
        float v = sum + bptr[0];
        g_gate[row] = 1.0f / (1.0f + __expf(-v));
    }
}

// ---------------------------------------------------------------------------
// Kernel 2: adj[e] = attr[e] * gate[col[e]]; optionally pass indices through
// as float (ids < 2^24 so exact). 4 edges/thread, 16B vector memops.
// Uniform branch on g_is64 selects int64 vs int32 index decoding.
// ---------------------------------------------------------------------------
template <bool FULL>
__global__ void edge_kernel(const void* __restrict__ eiv,
                            const float* __restrict__ attr,
                            float* __restrict__ out, int E) {
    const int is64 = g_is64;
    int g = blockIdx.x * blockDim.x + threadIdx.x;
    int e = g << 2;
    if (e >= E) return;

    if (e + 3 < E) {
        float4 av = reinterpret_cast<const float4*>(attr)[g];
        float4 adj, o0, o1;
        if (is64) {
            const long long* ei = (const long long*)eiv;
            const longlong2* r1p = reinterpret_cast<const longlong2*>(ei + E);
            longlong2 b0 = r1p[2 * g], b1 = r1p[2 * g + 1];
            adj.x = av.x * g_gate[(int)b0.x];
            adj.y = av.y * g_gate[(int)b0.y];
            adj.z = av.z * g_gate[(int)b1.x];
            adj.w = av.w * g_gate[(int)b1.y];
            if (FULL) {
                const longlong2* r0p = reinterpret_cast<const longlong2*>(ei);
                longlong2 a0 = r0p[2 * g], a1 = r0p[2 * g + 1];
                o0 = make_float4((float)a0.x, (float)a0.y, (float)a1.x, (float)a1.y);
                o1 = make_float4((float)b0.x, (float)b0.y, (float)b1.x, (float)b1.y);
            }
        } else {
            const int* ei = (const int*)eiv;
            int4 b = reinterpret_cast<const int4*>(ei + E)[g];
            adj.x = av.x * g_gate[b.x];
            adj.y = av.y * g_gate[b.y];
            adj.z = av.z * g_gate[b.z];
            adj.w = av.w * g_gate[b.w];
            if (FULL) {
                int4 a = reinterpret_cast<const int4*>(ei)[g];
                o0 = make_float4((float)a.x, (float)a.y, (float)a.z, (float)a.w);
                o1 = make_float4((float)b.x, (float)b.y, (float)b.z, (float)b.w);
            }
        }
        if (FULL) {
            reinterpret_cast<float4*>(out)[g] = o0;
            reinterpret_cast<float4*>(out + E)[g] = o1;
            reinterpret_cast<float4*>(out + 2 * (size_t)E)[g] = adj;
        } else {
            reinterpret_cast<float4*>(out)[g] = adj;
        }
    } else {
        for (int k = e; k < E; k++) {
            int c0, c1;
            if (is64) {
                const long long* ei = (const long long*)eiv;
                c0 = (int)ei[k];
                c1 = (int)ei[E + k];
            } else {
                const int* ei = (const int*)eiv;
                c0 = ei[k];
                c1 = ei[E + k];
            }
            float a = attr[k] * g_gate[c1];
            if (FULL) {
                out[k]                 = (float)c0;
                out[(size_t)E + k]     = (float)c1;
                out[2 * (size_t)E + k] = a;
            } else {
                out[k] = a;
            }
        }
    }
}

// ---------------------------------------------------------------------------
// Inputs (metadata order): x [N*D] f32, edge_index [2*E] (i32 or i64),
//                          edge_attr [E] f32, p [D] f32, b [1] f32
// ---------------------------------------------------------------------------
extern "C" void kernel_launch(void* const* d_in, const int* in_sizes, int n_in,
                              void* d_out, int out_size) {
    const float* x    = (const float*)d_in[0];
    const void*  ei   = d_in[1];
    const float* attr = (const float*)d_in[2];
    const float* p    = (const float*)d_in[3];
    const float* b    = (const float*)d_in[4];
    float* out = (float*)d_out;

    int ND = in_sizes[0];
    int E  = in_sizes[2];
    int D  = in_sizes[3];
    int N  = ND / D;

    // Kernel 0: index-width detection (writes g_is64).
    detect_kernel<<<1, 256>>>((const int*)ei, in_sizes[1]);

    // Kernel 1: per-node gates.
    int rows_per_block = 256 / 32;
    int gblocks = (N + rows_per_block - 1) / rows_per_block;
    gate_kernel<<<gblocks, 256>>>(x, p, b, N, D);

    // Kernel 2: edge scaling (+ optional index passthrough).
    int groups  = (E + 3) / 4;
    int eblocks = (groups + 255) / 256;
    if ((long long)out_size >= 3LL * E) {
        edge_kernel<true><<<eblocks, 256>>>(ei, attr, out, E);
    } else {
        edge_kernel<false><<<eblocks, 256>>>(ei, attr, out, E);
    }
}